// round 4
// baseline (speedup 1.0000x reference)
#include <cuda_runtime.h>
#include <cuda_bf16.h>
#include <stdint.h>

// Problem shape: N=50000 nodes, E=800000 edges, feature dims 128 -> 128 -> 64
#define MAXN 50016
#define MAXE 800000

// Scratch: static __device__ globals (allocation-free per harness rules)
__device__ int g_is64;                          // 1 if edge_index is int64, 0 if int32
__device__ __align__(16) int   g_cnt[MAXN];     // in-degree (excl. self-loop)
__device__ __align__(16) int   g_fill[MAXN];    // CSR fill counters
__device__ __align__(16) int   g_rowptr[MAXN];  // CSR row pointers
__device__ __align__(16) int   g_csr_src[MAXE]; // CSR: source node per in-edge
__device__ __align__(16) float g_dinv[MAXN];
__device__ __align__(16) float g_h1[MAXN * 128];   // (x @ W1) * dinv[row]
__device__ __align__(16) float g_acc1[MAXN * 128]; // aggregated layer-1 (pre-relu)
__device__ __align__(16) float g_h2[MAXN * 64];    // (relu(acc1) @ W2) * dinv[row]

// ---------------------------------------------------------------------------
// Edge-index dtype detection: int64 little-endian with values < 2^31 has every
// odd 32-bit word == 0. Random int32 node ids do not (P ~ (2e-5)^128).
// ---------------------------------------------------------------------------
__global__ void detect_kernel(const int* __restrict__ ei_w) {
    if (threadIdx.x == 0) {
        int is64 = 1;
        for (int i = 1; i < 256; i += 2)
            if (ei_w[i] != 0) { is64 = 0; break; }
        g_is64 = is64;
    }
}

__device__ __forceinline__ int edge_at(const void* ei, size_t idx) {
    return g_is64 ? (int)((const long long*)ei)[idx]
                  : ((const int*)ei)[idx];
}

// ---------------------------------------------------------------------------
// CSR build: histogram -> scan -> fill
// ---------------------------------------------------------------------------
__global__ void init_kernel(int n) {
    int i = blockIdx.x * blockDim.x + threadIdx.x;
    if (i < n) { g_cnt[i] = 0; g_fill[i] = 0; }
}

__global__ void count_kernel(const void* __restrict__ ei, int E, int N) {
    int e = blockIdx.x * blockDim.x + threadIdx.x;
    if (e < E) {
        int col = edge_at(ei, (size_t)E + e);
        if ((unsigned)col < (unsigned)N) atomicAdd(&g_cnt[col], 1);
    }
}

// Single-block exclusive scan of g_cnt -> g_rowptr
__global__ void scan_kernel(int N) {
    __shared__ int s[1024];
    const int t = threadIdx.x;
    const int chunk = (N + 1023) / 1024;
    const int start = t * chunk;

    int sum = 0;
    for (int i = 0; i < chunk; i++) {
        int idx = start + i;
        if (idx < N) sum += g_cnt[idx];
    }
    s[t] = sum;
    __syncthreads();
    for (int off = 1; off < 1024; off <<= 1) {
        int v = (t >= off) ? s[t - off] : 0;
        __syncthreads();
        s[t] += v;
        __syncthreads();
    }
    int run = (t > 0) ? s[t - 1] : 0;
    for (int i = 0; i < chunk; i++) {
        int idx = start + i;
        if (idx < N) {
            g_rowptr[idx] = run;
            run += g_cnt[idx];
        }
    }
}

__global__ void dinv_kernel(int n) {
    int i = blockIdx.x * blockDim.x + threadIdx.x;
    if (i < n) g_dinv[i] = rsqrtf((float)(g_cnt[i] + 1));  // +1 self-loop
}

__global__ void fill_kernel(const void* __restrict__ ei, int E, int N) {
    int e = blockIdx.x * blockDim.x + threadIdx.x;
    if (e < E) {
        int row = edge_at(ei, e);
        int col = edge_at(ei, (size_t)E + e);
        if ((unsigned)row < (unsigned)N && (unsigned)col < (unsigned)N) {
            int pos = g_rowptr[col] + atomicAdd(&g_fill[col], 1);
            g_csr_src[pos] = row;
        }
    }
}

// ---------------------------------------------------------------------------
// Fused GEMM: H = ((relu?)X @ W) * dinv[row]   (pre-scaled messages)
// NOUT = blockDim.x (one output column per thread), 8 rows per block.
// ---------------------------------------------------------------------------
template <int LAYER, int KD, int NOUT>
__global__ void gemm_kernel(const float* __restrict__ Xin,
                            const float* __restrict__ W,
                            int N) {
    constexpr int RT = 8;
    constexpr int KC = 64;
    __shared__ float xs[RT][KD];
    __shared__ float ws[KC][NOUT];

    const float* X = (LAYER == 1) ? Xin  : g_acc1;
    float*       H = (LAYER == 1) ? g_h1 : g_h2;

    const int t  = threadIdx.x;
    const int r0 = blockIdx.x * RT;

    for (int i = t; i < RT * KD; i += NOUT) {
        int r = i / KD, k = i % KD;
        int row = r0 + r;
        float v = (row < N) ? X[(size_t)row * KD + k] : 0.0f;
        if (LAYER == 2) v = fmaxf(v, 0.0f);
        xs[r][k] = v;
    }

    float acc[RT];
#pragma unroll
    for (int r = 0; r < RT; r++) acc[r] = 0.0f;

    for (int kc = 0; kc < KD; kc += KC) {
        __syncthreads();
        for (int i = t; i < KC * NOUT; i += NOUT) {
            int k = i / NOUT;
            ws[k][t] = W[(size_t)(kc + k) * NOUT + t];
        }
        __syncthreads();
#pragma unroll
        for (int k = 0; k < KC; k += 4) {
            float w0 = ws[k + 0][t];
            float w1 = ws[k + 1][t];
            float w2 = ws[k + 2][t];
            float w3 = ws[k + 3][t];
#pragma unroll
            for (int r = 0; r < RT; r++) {
                float4 xv = *reinterpret_cast<const float4*>(&xs[r][kc + k]);
                acc[r] = fmaf(xv.x, w0, acc[r]);
                acc[r] = fmaf(xv.y, w1, acc[r]);
                acc[r] = fmaf(xv.z, w2, acc[r]);
                acc[r] = fmaf(xv.w, w3, acc[r]);
            }
        }
    }

#pragma unroll
    for (int r = 0; r < RT; r++) {
        int row = r0 + r;
        if (row < N)
            H[(size_t)row * NOUT + t] = acc[r] * g_dinv[row];
    }
}

// ---------------------------------------------------------------------------
// Atomic-free aggregation: one warp per destination node.
//   ACC[col] = dinv[col] * ( hs[col] + sum_{src in in(col)} hs[src] ) + bias
// ---------------------------------------------------------------------------
template <int F>
__global__ void agg_kernel(const float* __restrict__ bias,
                           float* __restrict__ OUT2, int N) {
    const float* HS  = (F == 128) ? g_h1   : g_h2;
    float*       ACC = (F == 128) ? g_acc1 : OUT2;
    constexpr int V = F / 32;  // floats per lane (4 or 2)

    int col  = (blockIdx.x * blockDim.x + threadIdx.x) >> 5;
    int lane = threadIdx.x & 31;
    if (col >= N) return;

    const int start = g_rowptr[col];
    const int cnt   = g_cnt[col];

    float v[V];
    {
        const float* r = HS + (size_t)col * F + lane * V;
        if (V == 4) {
            float4 x = *reinterpret_cast<const float4*>(r);
            v[0] = x.x; v[1] = x.y; v[2] = x.z; v[3] = x.w;
        } else {
            float2 x = *reinterpret_cast<const float2*>(r);
            v[0] = x.x; v[1] = x.y;
        }
    }
    for (int j = 0; j < cnt; j++) {
        int src = __ldg(&g_csr_src[start + j]);
        const float* r = HS + (size_t)src * F + lane * V;
        if (V == 4) {
            float4 x = __ldg(reinterpret_cast<const float4*>(r));
            v[0] += x.x; v[1] += x.y; v[2] += x.z; v[3] += x.w;
        } else {
            float2 x = __ldg(reinterpret_cast<const float2*>(r));
            v[0] += x.x; v[1] += x.y;
        }
    }

    const float d = g_dinv[col];
    float* o = ACC + (size_t)col * F + lane * V;
    if (V == 4) {
        float4 b = *reinterpret_cast<const float4*>(bias + lane * 4);
        float4 w;
        w.x = fmaf(v[0], d, b.x);
        w.y = fmaf(v[1], d, b.y);
        w.z = fmaf(v[2], d, b.z);
        w.w = fmaf(v[3], d, b.w);
        *reinterpret_cast<float4*>(o) = w;
    } else {
        float2 b = *reinterpret_cast<const float2*>(bias + lane * 2);
        float2 w;
        w.x = fmaf(v[0], d, b.x);
        w.y = fmaf(v[1], d, b.y);
        *reinterpret_cast<float2*>(o) = w;
    }
}

// ---------------------------------------------------------------------------
// Launch
// ---------------------------------------------------------------------------
extern "C" void kernel_launch(void* const* d_in, const int* in_sizes, int n_in,
                              void* d_out, int out_size) {
    const float* x   = (const float*)d_in[0];
    const void*  ei  = d_in[1];
    // d_in[2]=edge_label, d_in[3]=edge_label_index: unused by reference()
    const float* W1  = (const float*)d_in[4];
    const float* b1  = (const float*)d_in[5];
    const float* W2  = (const float*)d_in[6];
    const float* b2  = (const float*)d_in[7];
    float*       out = (float*)d_out;

    const int N = in_sizes[0] / 128;
    const int E = in_sizes[1] / 2;

    // Edge dtype detection + CSR build + normalization
    detect_kernel<<<1, 32>>>((const int*)ei);
    init_kernel<<<(N + 255) / 256, 256>>>(N);
    count_kernel<<<(E + 255) / 256, 256>>>(ei, E, N);
    scan_kernel<<<1, 1024>>>(N);
    dinv_kernel<<<(N + 255) / 256, 256>>>(N);
    fill_kernel<<<(E + 255) / 256, 256>>>(ei, E, N);

    // Layer 1
    gemm_kernel<1, 128, 128><<<(N + 7) / 8, 128>>>(x, W1, N);
    agg_kernel<128><<<(N * 32 + 255) / 256, 256>>>(b1, nullptr, N);

    // Layer 2
    gemm_kernel<2, 128, 64><<<(N + 7) / 8, 64>>>(nullptr, W2, N);
    agg_kernel<64><<<(N * 32 + 255) / 256, 256>>>(b2, out, N);
}

// round 5
// speedup vs baseline: 1.2801x; 1.2801x over previous
#include <cuda_runtime.h>
#include <cuda_bf16.h>
#include <stdint.h>

// Problem shape: N=50000 nodes, E=800000 edges, feature dims 128 -> 128 -> 64
#define MAXN 50176              // padded to multiple of 1024
#define MAXE 800000
#define MAXB ((MAXN + 1023) / 1024)

// Scratch: static __device__ globals (allocation-free per harness rules)
__device__ int g_is64;                          // 1 if edge_index is int64
__device__ __align__(16) int   g_cnt[MAXN];     // in-degree (excl. self-loop)
__device__ __align__(16) int   g_fill[MAXN];    // CSR fill counters
__device__ __align__(16) int   g_rowptr[MAXN];  // CSR row pointers
__device__ __align__(16) int   g_bsum[MAXB];    // per-block sums for scan
__device__ __align__(16) int   g_boff[MAXB];    // per-block exclusive offsets
__device__ __align__(16) int   g_csr_src[MAXE]; // CSR: source node per in-edge
__device__ __align__(16) float g_dinv[MAXN];
__device__ __align__(16) float g_h1[MAXN * 128];   // (x @ W1) * dinv[row]
__device__ __align__(16) float g_acc1[MAXN * 128]; // aggregated layer-1 (pre-relu)
__device__ __align__(16) float g_h2[MAXN * 64];    // (relu(acc1) @ W2) * dinv[row]

// ---------------------------------------------------------------------------
// Edge-index dtype detection: int64 little-endian with values < 2^31 has every
// odd 32-bit word == 0. Random int32 node ids do not.
// ---------------------------------------------------------------------------
__global__ void detect_kernel(const int* __restrict__ ei_w) {
    if (threadIdx.x == 0) {
        int is64 = 1;
        for (int i = 1; i < 256; i += 2)
            if (ei_w[i] != 0) { is64 = 0; break; }
        g_is64 = is64;
    }
}

__device__ __forceinline__ int edge_at(const void* ei, size_t idx) {
    return g_is64 ? (int)((const long long*)ei)[idx]
                  : ((const int*)ei)[idx];
}

// ---------------------------------------------------------------------------
// CSR build: histogram -> multi-block scan -> fill
// ---------------------------------------------------------------------------
__global__ void init_kernel(int n) {
    int i = blockIdx.x * blockDim.x + threadIdx.x;
    if (i < n) { g_cnt[i] = 0; g_fill[i] = 0; }
}

__global__ void count_kernel(const void* __restrict__ ei, int E, int N) {
    int e = blockIdx.x * blockDim.x + threadIdx.x;
    if (e < E) {
        int col = edge_at(ei, (size_t)E + e);
        if ((unsigned)col < (unsigned)N) atomicAdd(&g_cnt[col], 1);
    }
}

// Phase 1: per-block (1024-elem) sums
__global__ void __launch_bounds__(1024) scan_bsum_kernel(int N) {
    __shared__ int wsum[32];
    int b = blockIdx.x, t = threadIdx.x;
    int gid = b * 1024 + t;
    int v = (gid < N) ? g_cnt[gid] : 0;
    // warp reduce
    for (int o = 16; o > 0; o >>= 1) v += __shfl_down_sync(~0u, v, o);
    if ((t & 31) == 0) wsum[t >> 5] = v;
    __syncthreads();
    if (t < 32) {
        int s = wsum[t];
        for (int o = 16; o > 0; o >>= 1) s += __shfl_down_sync(~0u, s, o);
        if (t == 0) g_bsum[b] = s;
    }
}

// Phase 2: exclusive scan of block sums (nb <= MAXB, single small block)
__global__ void scan_boff_kernel(int nb) {
    __shared__ int s[64];
    int t = threadIdx.x;  // 64 threads
    s[t] = (t < nb) ? g_bsum[t] : 0;
    __syncthreads();
    for (int off = 1; off < 64; off <<= 1) {
        int v = (t >= off) ? s[t - off] : 0;
        __syncthreads();
        s[t] += v;
        __syncthreads();
    }
    if (t < nb) g_boff[t] = (t > 0) ? s[t - 1] : 0;
}

// Phase 3: local exclusive scan (shuffle) + block offset -> rowptr
__global__ void __launch_bounds__(1024) scan_local_kernel(int N) {
    __shared__ int wsum[32];
    int b = blockIdx.x, t = threadIdx.x;
    int gid = b * 1024 + t;
    int lane = t & 31, w = t >> 5;
    int v = (gid < N) ? g_cnt[gid] : 0;
    int s = v;
    // warp inclusive scan
    for (int o = 1; o < 32; o <<= 1) {
        int u = __shfl_up_sync(~0u, s, o);
        if (lane >= o) s += u;
    }
    if (lane == 31) wsum[w] = s;
    __syncthreads();
    if (t < 32) {
        int ws = wsum[t];
        for (int o = 1; o < 32; o <<= 1) {
            int u = __shfl_up_sync(~0u, ws, o);
            if (t >= o) ws += u;
        }
        wsum[t] = ws;
    }
    __syncthreads();
    int excl = s - v + ((w > 0) ? wsum[w - 1] : 0) + g_boff[b];
    if (gid < N) g_rowptr[gid] = excl;
}

__global__ void dinv_kernel(int n) {
    int i = blockIdx.x * blockDim.x + threadIdx.x;
    if (i < n) g_dinv[i] = rsqrtf((float)(g_cnt[i] + 1));  // +1 self-loop
}

__global__ void fill_kernel(const void* __restrict__ ei, int E, int N) {
    int e = blockIdx.x * blockDim.x + threadIdx.x;
    if (e < E) {
        int row = edge_at(ei, e);
        int col = edge_at(ei, (size_t)E + e);
        if ((unsigned)row < (unsigned)N && (unsigned)col < (unsigned)N) {
            int pos = g_rowptr[col] + atomicAdd(&g_fill[col], 1);
            g_csr_src[pos] = row;
        }
    }
}

// ---------------------------------------------------------------------------
// Fused GEMM: H = ((relu?)X @ W) * dinv[row]   (pre-scaled messages)
// ---------------------------------------------------------------------------
template <int LAYER, int KD, int NOUT>
__global__ void __launch_bounds__(NOUT) gemm_kernel(const float* __restrict__ Xin,
                                                    const float* __restrict__ W,
                                                    int N) {
    constexpr int RT = 8;
    constexpr int KC = 64;
    __shared__ float xs[RT][KD];
    __shared__ float ws[KC][NOUT];

    const float* X = (LAYER == 1) ? Xin  : g_acc1;
    float*       H = (LAYER == 1) ? g_h1 : g_h2;

    const int t  = threadIdx.x;
    const int r0 = blockIdx.x * RT;

    for (int i = t; i < RT * KD; i += NOUT) {
        int r = i / KD, k = i % KD;
        int row = r0 + r;
        float v = (row < N) ? X[(size_t)row * KD + k] : 0.0f;
        if (LAYER == 2) v = fmaxf(v, 0.0f);
        xs[r][k] = v;
    }

    float acc[RT];
#pragma unroll
    for (int r = 0; r < RT; r++) acc[r] = 0.0f;

    for (int kc = 0; kc < KD; kc += KC) {
        __syncthreads();
        for (int i = t; i < KC * NOUT; i += NOUT) {
            int k = i / NOUT;
            ws[k][t] = W[(size_t)(kc + k) * NOUT + t];
        }
        __syncthreads();
#pragma unroll
        for (int k = 0; k < KC; k += 4) {
            float w0 = ws[k + 0][t];
            float w1 = ws[k + 1][t];
            float w2 = ws[k + 2][t];
            float w3 = ws[k + 3][t];
#pragma unroll
            for (int r = 0; r < RT; r++) {
                float4 xv = *reinterpret_cast<const float4*>(&xs[r][kc + k]);
                acc[r] = fmaf(xv.x, w0, acc[r]);
                acc[r] = fmaf(xv.y, w1, acc[r]);
                acc[r] = fmaf(xv.z, w2, acc[r]);
                acc[r] = fmaf(xv.w, w3, acc[r]);
            }
        }
    }

#pragma unroll
    for (int r = 0; r < RT; r++) {
        int row = r0 + r;
        if (row < N)
            H[(size_t)row * NOUT + t] = acc[r] * g_dinv[row];
    }
}

// ---------------------------------------------------------------------------
// Atomic-free aggregation: one warp per destination node, 4-way unrolled
// gather for MLP.  ACC[col] = dinv[col]*(hs[col] + sum hs[src]) + bias
// ---------------------------------------------------------------------------
template <int F>
__global__ void __launch_bounds__(256) agg_kernel(const float* __restrict__ bias,
                                                  float* __restrict__ OUT2, int N) {
    const float* HS  = (F == 128) ? g_h1   : g_h2;
    float*       ACC = (F == 128) ? g_acc1 : OUT2;
    constexpr int V = F / 32;  // floats per lane (4 or 2)

    int col  = (blockIdx.x * blockDim.x + threadIdx.x) >> 5;
    int lane = threadIdx.x & 31;
    if (col >= N) return;

    const int start = g_rowptr[col];
    const int cnt   = g_cnt[col];

    float v[V];
    {
        const float* r = HS + (size_t)col * F + lane * V;
        if (V == 4) {
            float4 x = *reinterpret_cast<const float4*>(r);
            v[0] = x.x; v[1] = x.y; v[2] = x.z; v[3] = x.w;
        } else {
            float2 x = *reinterpret_cast<const float2*>(r);
            v[0] = x.x; v[1] = x.y;
        }
    }

    int j = 0;
    // 4-way unrolled: 4 independent gathers in flight per lane
    for (; j + 4 <= cnt; j += 4) {
        int s0 = __ldg(&g_csr_src[start + j + 0]);
        int s1 = __ldg(&g_csr_src[start + j + 1]);
        int s2 = __ldg(&g_csr_src[start + j + 2]);
        int s3 = __ldg(&g_csr_src[start + j + 3]);
        if (V == 4) {
            float4 x0 = __ldg(reinterpret_cast<const float4*>(HS + (size_t)s0 * F + lane * 4));
            float4 x1 = __ldg(reinterpret_cast<const float4*>(HS + (size_t)s1 * F + lane * 4));
            float4 x2 = __ldg(reinterpret_cast<const float4*>(HS + (size_t)s2 * F + lane * 4));
            float4 x3 = __ldg(reinterpret_cast<const float4*>(HS + (size_t)s3 * F + lane * 4));
            v[0] += x0.x + x1.x + x2.x + x3.x;
            v[1] += x0.y + x1.y + x2.y + x3.y;
            v[2] += x0.z + x1.z + x2.z + x3.z;
            v[3] += x0.w + x1.w + x2.w + x3.w;
        } else {
            float2 x0 = __ldg(reinterpret_cast<const float2*>(HS + (size_t)s0 * F + lane * 2));
            float2 x1 = __ldg(reinterpret_cast<const float2*>(HS + (size_t)s1 * F + lane * 2));
            float2 x2 = __ldg(reinterpret_cast<const float2*>(HS + (size_t)s2 * F + lane * 2));
            float2 x3 = __ldg(reinterpret_cast<const float2*>(HS + (size_t)s3 * F + lane * 2));
            v[0] += x0.x + x1.x + x2.x + x3.x;
            v[1] += x0.y + x1.y + x2.y + x3.y;
        }
    }
    for (; j < cnt; j++) {
        int src = __ldg(&g_csr_src[start + j]);
        const float* r = HS + (size_t)src * F + lane * V;
        if (V == 4) {
            float4 x = __ldg(reinterpret_cast<const float4*>(r));
            v[0] += x.x; v[1] += x.y; v[2] += x.z; v[3] += x.w;
        } else {
            float2 x = __ldg(reinterpret_cast<const float2*>(r));
            v[0] += x.x; v[1] += x.y;
        }
    }

    const float d = g_dinv[col];
    float* o = ACC + (size_t)col * F + lane * V;
    if (V == 4) {
        float4 b = *reinterpret_cast<const float4*>(bias + lane * 4);
        float4 w;
        w.x = fmaf(v[0], d, b.x);
        w.y = fmaf(v[1], d, b.y);
        w.z = fmaf(v[2], d, b.z);
        w.w = fmaf(v[3], d, b.w);
        *reinterpret_cast<float4*>(o) = w;
    } else {
        float2 b = *reinterpret_cast<const float2*>(bias + lane * 2);
        float2 w;
        w.x = fmaf(v[0], d, b.x);
        w.y = fmaf(v[1], d, b.y);
        *reinterpret_cast<float2*>(o) = w;
    }
}

// ---------------------------------------------------------------------------
// Launch
// ---------------------------------------------------------------------------
extern "C" void kernel_launch(void* const* d_in, const int* in_sizes, int n_in,
                              void* d_out, int out_size) {
    const float* x   = (const float*)d_in[0];
    const void*  ei  = d_in[1];
    // d_in[2]=edge_label, d_in[3]=edge_label_index: unused by reference()
    const float* W1  = (const float*)d_in[4];
    const float* b1  = (const float*)d_in[5];
    const float* W2  = (const float*)d_in[6];
    const float* b2  = (const float*)d_in[7];
    float*       out = (float*)d_out;

    const int N  = in_sizes[0] / 128;
    const int E  = in_sizes[1] / 2;
    const int NB = (N + 1023) / 1024;

    // Edge dtype detection + CSR build + normalization
    detect_kernel<<<1, 32>>>((const int*)ei);
    init_kernel<<<(N + 255) / 256, 256>>>(N);
    count_kernel<<<(E + 255) / 256, 256>>>(ei, E, N);
    scan_bsum_kernel<<<NB, 1024>>>(N);
    scan_boff_kernel<<<1, 64>>>(NB);
    scan_local_kernel<<<NB, 1024>>>(N);
    dinv_kernel<<<(N + 255) / 256, 256>>>(N);
    fill_kernel<<<(E + 255) / 256, 256>>>(ei, E, N);

    // Layer 1
    gemm_kernel<1, 128, 128><<<(N + 7) / 8, 128>>>(x, W1, N);
    agg_kernel<128><<<(N * 32 + 255) / 256, 256>>>(b1, nullptr, N);

    // Layer 2
    gemm_kernel<2, 128, 64><<<(N + 7) / 8, 64>>>(nullptr, W2, N);
    agg_kernel<64><<<(N * 32 + 255) / 256, 256>>>(b2, out, N);
}

// round 6
// speedup vs baseline: 2.0063x; 1.5673x over previous
#include <cuda_runtime.h>
#include <cuda_bf16.h>
#include <mma.h>
#include <stdint.h>

using namespace nvcuda;

// Problem shape: N=50000 nodes, E=800000 edges, feature dims 128 -> 128 -> 64
#define MAXN 50176              // padded
#define MAXE 800000
#define MAXB ((MAXN + 1023) / 1024)

__device__ int g_is64;
__device__ __align__(16) int   g_cnt[MAXN];
__device__ __align__(16) int   g_fill[MAXN];
__device__ __align__(16) int   g_rowptr[MAXN];
__device__ __align__(16) int   g_bsum[MAXB];
__device__ __align__(16) int   g_boff[MAXB];
__device__ __align__(16) int   g_csr_src[MAXE];
__device__ __align__(16) float g_dinv[MAXN];
__device__ __align__(16) float g_h1[MAXN * 128];   // x @ W1 (unscaled)
__device__ __align__(16) float g_acc1[MAXN * 128]; // relu(aggregated layer-1)
__device__ __align__(16) float g_h2[MAXN * 64];    // relu(acc1) @ W2 (unscaled)

// ---------------------------------------------------------------------------
// Edge-index dtype detection (int64 LE with small values => odd words all 0)
// ---------------------------------------------------------------------------
__global__ void detect_kernel(const int* __restrict__ ei_w) {
    if (threadIdx.x == 0) {
        int is64 = 1;
        for (int i = 1; i < 256; i += 2)
            if (ei_w[i] != 0) { is64 = 0; break; }
        g_is64 = is64;
    }
}

__device__ __forceinline__ int edge_at(const void* ei, size_t idx) {
    return g_is64 ? (int)((const long long*)ei)[idx]
                  : ((const int*)ei)[idx];
}

// ---------------------------------------------------------------------------
// CSR build
// ---------------------------------------------------------------------------
__global__ void init_kernel(int n) {
    int i = blockIdx.x * blockDim.x + threadIdx.x;
    if (i < n) { g_cnt[i] = 0; g_fill[i] = 0; }
}

__global__ void count_kernel(const void* __restrict__ ei, int E, int N) {
    int e = blockIdx.x * blockDim.x + threadIdx.x;
    if (e < E) {
        int col = edge_at(ei, (size_t)E + e);
        if ((unsigned)col < (unsigned)N) atomicAdd(&g_cnt[col], 1);
    }
}

__global__ void __launch_bounds__(1024) scan_bsum_kernel(int N) {
    __shared__ int wsum[32];
    int b = blockIdx.x, t = threadIdx.x;
    int gid = b * 1024 + t;
    int v = (gid < N) ? g_cnt[gid] : 0;
    for (int o = 16; o > 0; o >>= 1) v += __shfl_down_sync(~0u, v, o);
    if ((t & 31) == 0) wsum[t >> 5] = v;
    __syncthreads();
    if (t < 32) {
        int s = wsum[t];
        for (int o = 16; o > 0; o >>= 1) s += __shfl_down_sync(~0u, s, o);
        if (t == 0) g_bsum[b] = s;
    }
}

__global__ void scan_boff_kernel(int nb) {
    __shared__ int s[64];
    int t = threadIdx.x;
    s[t] = (t < nb) ? g_bsum[t] : 0;
    __syncthreads();
    for (int off = 1; off < 64; off <<= 1) {
        int v = (t >= off) ? s[t - off] : 0;
        __syncthreads();
        s[t] += v;
        __syncthreads();
    }
    if (t < nb) g_boff[t] = (t > 0) ? s[t - 1] : 0;
}

__global__ void __launch_bounds__(1024) scan_local_kernel(int N) {
    __shared__ int wsum[32];
    int b = blockIdx.x, t = threadIdx.x;
    int gid = b * 1024 + t;
    int lane = t & 31, w = t >> 5;
    int v = (gid < N) ? g_cnt[gid] : 0;
    int s = v;
    for (int o = 1; o < 32; o <<= 1) {
        int u = __shfl_up_sync(~0u, s, o);
        if (lane >= o) s += u;
    }
    if (lane == 31) wsum[w] = s;
    __syncthreads();
    if (t < 32) {
        int ws = wsum[t];
        for (int o = 1; o < 32; o <<= 1) {
            int u = __shfl_up_sync(~0u, ws, o);
            if (t >= o) ws += u;
        }
        wsum[t] = ws;
    }
    __syncthreads();
    int excl = s - v + ((w > 0) ? wsum[w - 1] : 0) + g_boff[b];
    if (gid < N) g_rowptr[gid] = excl;
}

__global__ void dinv_kernel(int n) {
    int i = blockIdx.x * blockDim.x + threadIdx.x;
    if (i < n) g_dinv[i] = rsqrtf((float)(g_cnt[i] + 1));
}

__global__ void fill_kernel(const void* __restrict__ ei, int E, int N) {
    int e = blockIdx.x * blockDim.x + threadIdx.x;
    if (e < E) {
        int row = edge_at(ei, e);
        int col = edge_at(ei, (size_t)E + e);
        if ((unsigned)row < (unsigned)N && (unsigned)col < (unsigned)N) {
            int pos = g_rowptr[col] + atomicAdd(&g_fill[col], 1);
            g_csr_src[pos] = row;
        }
    }
}

// ---------------------------------------------------------------------------
// Tensor-core GEMM (tf32 wmma m16n16k8): H = X @ W  (no scaling/epilogue).
// Block = 128 threads = 4 warps; each warp owns a 16-row stripe x NOUT cols.
// W chunk (64 x NOUT) staged in shared, pre-rounded to tf32.
// ---------------------------------------------------------------------------
template <int LAYER, int NOUT>
__global__ void __launch_bounds__(128) gemm_tc_kernel(const float* __restrict__ Xin,
                                                      const float* __restrict__ W,
                                                      int N) {
    constexpr int KD = 128, KC = 64;
    __shared__ __align__(16) float ws[KC * NOUT];

    const float* X = (LAYER == 1) ? Xin  : g_acc1;
    float*       H = (LAYER == 1) ? g_h1 : g_h2;

    const int warp = threadIdx.x >> 5;
    const int lane = threadIdx.x & 31;
    const int row0 = blockIdx.x * 64 + warp * 16;
    const bool active = (row0 + 16 <= N);

    wmma::fragment<wmma::accumulator, 16, 16, 8, float> c[NOUT / 16];
#pragma unroll
    for (int i = 0; i < NOUT / 16; i++) wmma::fill_fragment(c[i], 0.0f);

    for (int kc = 0; kc < KD; kc += KC) {
        __syncthreads();
        for (int i = threadIdx.x; i < KC * NOUT; i += 128)
            ws[i] = wmma::__float_to_tf32(W[(size_t)(kc + i / NOUT) * NOUT + (i % NOUT)]);
        __syncthreads();
        if (active) {
#pragma unroll
            for (int k = 0; k < KC; k += 8) {
                wmma::fragment<wmma::matrix_a, 16, 16, 8, wmma::precision::tf32, wmma::row_major> a;
                wmma::load_matrix_sync(a, X + (size_t)row0 * KD + kc + k, KD);
#pragma unroll
                for (int i = 0; i < a.num_elements; i++)
                    a.x[i] = wmma::__float_to_tf32(a.x[i]);
#pragma unroll
                for (int nt = 0; nt < NOUT / 16; nt++) {
                    wmma::fragment<wmma::matrix_b, 16, 16, 8, wmma::precision::tf32, wmma::row_major> b;
                    wmma::load_matrix_sync(b, ws + k * NOUT + nt * 16, NOUT);
                    wmma::mma_sync(c[nt], a, b, c[nt]);
                }
            }
        }
    }

    if (active) {
#pragma unroll
        for (int nt = 0; nt < NOUT / 16; nt++)
            wmma::store_matrix_sync(H + (size_t)row0 * NOUT + nt * 16, c[nt],
                                    NOUT, wmma::mem_row_major);
    } else if (row0 < N) {
        // scalar tail (only if N % 16 != 0)
        for (int r = row0; r < N; r++)
            for (int col = lane; col < NOUT; col += 32) {
                float s = 0.0f;
                for (int k = 0; k < KD; k++)
                    s += X[(size_t)r * KD + k] * W[(size_t)k * NOUT + col];
                H[(size_t)r * NOUT + col] = s;
            }
    }
}

// ---------------------------------------------------------------------------
// Atomic-free aggregation, one warp per destination node.
//   ACC[col] = (relu?)( dinv[col]*( h[col]*dinv[col] + sum h[src]*dinv[src] ) + bias )
// ---------------------------------------------------------------------------
template <int F, bool RELU>
__global__ void __launch_bounds__(256) agg_kernel(const float* __restrict__ bias,
                                                  float* __restrict__ OUT2, int N) {
    const float* HS  = (F == 128) ? g_h1   : g_h2;
    float*       ACC = (F == 128) ? g_acc1 : OUT2;
    constexpr int V = F / 32;

    int col  = (blockIdx.x * blockDim.x + threadIdx.x) >> 5;
    int lane = threadIdx.x & 31;
    if (col >= N) return;

    const int   start = g_rowptr[col];
    const int   cnt   = g_cnt[col];
    const float d     = g_dinv[col];

    float v[V];
    {   // self-loop term: h[col] * dinv[col]
        const float* r = HS + (size_t)col * F + lane * V;
        if (V == 4) {
            float4 x = *reinterpret_cast<const float4*>(r);
            v[0] = x.x * d; v[1] = x.y * d; v[2] = x.z * d; v[3] = x.w * d;
        } else {
            float2 x = *reinterpret_cast<const float2*>(r);
            v[0] = x.x * d; v[1] = x.y * d;
        }
    }

    int j = 0;
    for (; j + 4 <= cnt; j += 4) {
        int s0 = __ldg(&g_csr_src[start + j + 0]);
        int s1 = __ldg(&g_csr_src[start + j + 1]);
        int s2 = __ldg(&g_csr_src[start + j + 2]);
        int s3 = __ldg(&g_csr_src[start + j + 3]);
        float d0 = __ldg(&g_dinv[s0]);
        float d1 = __ldg(&g_dinv[s1]);
        float d2 = __ldg(&g_dinv[s2]);
        float d3 = __ldg(&g_dinv[s3]);
        if (V == 4) {
            float4 x0 = __ldg(reinterpret_cast<const float4*>(HS + (size_t)s0 * F + lane * 4));
            float4 x1 = __ldg(reinterpret_cast<const float4*>(HS + (size_t)s1 * F + lane * 4));
            float4 x2 = __ldg(reinterpret_cast<const float4*>(HS + (size_t)s2 * F + lane * 4));
            float4 x3 = __ldg(reinterpret_cast<const float4*>(HS + (size_t)s3 * F + lane * 4));
            v[0] = fmaf(x0.x, d0, fmaf(x1.x, d1, fmaf(x2.x, d2, fmaf(x3.x, d3, v[0]))));
            v[1] = fmaf(x0.y, d0, fmaf(x1.y, d1, fmaf(x2.y, d2, fmaf(x3.y, d3, v[1]))));
            v[2] = fmaf(x0.z, d0, fmaf(x1.z, d1, fmaf(x2.z, d2, fmaf(x3.z, d3, v[2]))));
            v[3] = fmaf(x0.w, d0, fmaf(x1.w, d1, fmaf(x2.w, d2, fmaf(x3.w, d3, v[3]))));
        } else {
            float2 x0 = __ldg(reinterpret_cast<const float2*>(HS + (size_t)s0 * F + lane * 2));
            float2 x1 = __ldg(reinterpret_cast<const float2*>(HS + (size_t)s1 * F + lane * 2));
            float2 x2 = __ldg(reinterpret_cast<const float2*>(HS + (size_t)s2 * F + lane * 2));
            float2 x3 = __ldg(reinterpret_cast<const float2*>(HS + (size_t)s3 * F + lane * 2));
            v[0] = fmaf(x0.x, d0, fmaf(x1.x, d1, fmaf(x2.x, d2, fmaf(x3.x, d3, v[0]))));
            v[1] = fmaf(x0.y, d0, fmaf(x1.y, d1, fmaf(x2.y, d2, fmaf(x3.y, d3, v[1]))));
        }
    }
    for (; j < cnt; j++) {
        int src = __ldg(&g_csr_src[start + j]);
        float ds = __ldg(&g_dinv[src]);
        const float* r = HS + (size_t)src * F + lane * V;
        if (V == 4) {
            float4 x = __ldg(reinterpret_cast<const float4*>(r));
            v[0] = fmaf(x.x, ds, v[0]); v[1] = fmaf(x.y, ds, v[1]);
            v[2] = fmaf(x.z, ds, v[2]); v[3] = fmaf(x.w, ds, v[3]);
        } else {
            float2 x = __ldg(reinterpret_cast<const float2*>(r));
            v[0] = fmaf(x.x, ds, v[0]); v[1] = fmaf(x.y, ds, v[1]);
        }
    }

    float* o = ACC + (size_t)col * F + lane * V;
    if (V == 4) {
        float4 b = *reinterpret_cast<const float4*>(bias + lane * 4);
        float4 w;
        w.x = fmaf(v[0], d, b.x); w.y = fmaf(v[1], d, b.y);
        w.z = fmaf(v[2], d, b.z); w.w = fmaf(v[3], d, b.w);
        if (RELU) {
            w.x = fmaxf(w.x, 0.0f); w.y = fmaxf(w.y, 0.0f);
            w.z = fmaxf(w.z, 0.0f); w.w = fmaxf(w.w, 0.0f);
        }
        *reinterpret_cast<float4*>(o) = w;
    } else {
        float2 b = *reinterpret_cast<const float2*>(bias + lane * 2);
        float2 w;
        w.x = fmaf(v[0], d, b.x); w.y = fmaf(v[1], d, b.y);
        if (RELU) { w.x = fmaxf(w.x, 0.0f); w.y = fmaxf(w.y, 0.0f); }
        *reinterpret_cast<float2*>(o) = w;
    }
}

// ---------------------------------------------------------------------------
// Launch
// ---------------------------------------------------------------------------
extern "C" void kernel_launch(void* const* d_in, const int* in_sizes, int n_in,
                              void* d_out, int out_size) {
    const float* x   = (const float*)d_in[0];
    const void*  ei  = d_in[1];
    const float* W1  = (const float*)d_in[4];
    const float* b1  = (const float*)d_in[5];
    const float* W2  = (const float*)d_in[6];
    const float* b2  = (const float*)d_in[7];
    float*       out = (float*)d_out;

    const int N  = in_sizes[0] / 128;
    const int E  = in_sizes[1] / 2;
    const int NB = (N + 1023) / 1024;

    detect_kernel<<<1, 32>>>((const int*)ei);
    init_kernel<<<(N + 255) / 256, 256>>>(N);
    count_kernel<<<(E + 255) / 256, 256>>>(ei, E, N);
    scan_bsum_kernel<<<NB, 1024>>>(N);
    scan_boff_kernel<<<1, 64>>>(NB);
    scan_local_kernel<<<NB, 1024>>>(N);
    dinv_kernel<<<(N + 255) / 256, 256>>>(N);
    fill_kernel<<<(E + 255) / 256, 256>>>(ei, E, N);

    // Layer 1: h1 = x @ W1 (tf32 TC); acc1 = relu(agg(h1) + b1)
    gemm_tc_kernel<1, 128><<<(N + 63) / 64, 128>>>(x, W1, N);
    agg_kernel<128, true><<<(N * 32 + 255) / 256, 256>>>(b1, nullptr, N);

    // Layer 2: h2 = acc1 @ W2 (tf32 TC); out = agg(h2) + b2
    gemm_tc_kernel<2, 64><<<(N + 63) / 64, 128>>>(nullptr, W2, N);
    agg_kernel<64, false><<<(N * 32 + 255) / 256, 256>>>(b2, out, N);
}

// round 8
// speedup vs baseline: 2.1602x; 1.0767x over previous
#include <cuda_runtime.h>
#include <cuda_fp16.h>
#include <mma.h>
#include <stdint.h>

using namespace nvcuda;

// Problem shape: N=50000 nodes, E=800000 edges, feature dims 128 -> 128 -> 64
#define MAXN 50176
#define MAXE 800000
#define MAXB ((MAXN + 1023) / 1024)

struct __align__(8) half2x2 { __half2 a, b; };

__device__ int g_is64;
__device__ __align__(16) int    g_cnt[MAXN];
__device__ __align__(16) int    g_fill[MAXN];
__device__ __align__(16) int    g_rowptr[MAXN];
__device__ __align__(16) int    g_bsum[MAXB];
__device__ __align__(16) int    g_boff[MAXB];
__device__ __align__(16) int    g_csr_src[MAXE];
__device__ __align__(16) float  g_dinv[MAXN];
__device__ __align__(16) __half g_h1[MAXN * 128];   // (x @ W1) * dinv[row], fp16
__device__ __align__(16) float  g_acc1[MAXN * 128]; // relu(aggregated layer-1), fp32
__device__ __align__(16) __half g_h2[MAXN * 64];    // (acc1 @ W2) * dinv[row], fp16

// ---------------------------------------------------------------------------
// Edge-index dtype detection (int64 LE with small values => odd words all 0)
// ---------------------------------------------------------------------------
__global__ void detect_kernel(const int* __restrict__ ei_w) {
    if (threadIdx.x == 0) {
        int is64 = 1;
        for (int i = 1; i < 256; i += 2)
            if (ei_w[i] != 0) { is64 = 0; break; }
        g_is64 = is64;
    }
}

__device__ __forceinline__ int edge_at(const void* ei, size_t idx) {
    return g_is64 ? (int)((const long long*)ei)[idx]
                  : ((const int*)ei)[idx];
}

// ---------------------------------------------------------------------------
// CSR build
// ---------------------------------------------------------------------------
__global__ void init_kernel(int n) {
    int i = blockIdx.x * blockDim.x + threadIdx.x;
    if (i < n) { g_cnt[i] = 0; g_fill[i] = 0; }
}

__global__ void count_kernel(const void* __restrict__ ei, int E, int N) {
    int e = blockIdx.x * blockDim.x + threadIdx.x;
    if (e < E) {
        int col = edge_at(ei, (size_t)E + e);
        if ((unsigned)col < (unsigned)N) atomicAdd(&g_cnt[col], 1);
    }
}

__global__ void __launch_bounds__(1024) scan_bsum_kernel(int N) {
    __shared__ int wsum[32];
    int b = blockIdx.x, t = threadIdx.x;
    int gid = b * 1024 + t;
    int v = (gid < N) ? g_cnt[gid] : 0;
    for (int o = 16; o > 0; o >>= 1) v += __shfl_down_sync(~0u, v, o);
    if ((t & 31) == 0) wsum[t >> 5] = v;
    __syncthreads();
    if (t < 32) {
        int s = wsum[t];
        for (int o = 16; o > 0; o >>= 1) s += __shfl_down_sync(~0u, s, o);
        if (t == 0) g_bsum[b] = s;
    }
}

__global__ void scan_boff_kernel(int nb) {
    __shared__ int s[64];
    int t = threadIdx.x;
    s[t] = (t < nb) ? g_bsum[t] : 0;
    __syncthreads();
    for (int off = 1; off < 64; off <<= 1) {
        int v = (t >= off) ? s[t - off] : 0;
        __syncthreads();
        s[t] += v;
        __syncthreads();
    }
    if (t < nb) g_boff[t] = (t > 0) ? s[t - 1] : 0;
}

// local scan -> rowptr, fused dinv computation
__global__ void __launch_bounds__(1024) scan_local_kernel(int N) {
    __shared__ int wsum[32];
    int b = blockIdx.x, t = threadIdx.x;
    int gid = b * 1024 + t;
    int lane = t & 31, w = t >> 5;
    int v = (gid < N) ? g_cnt[gid] : 0;
    int s = v;
    for (int o = 1; o < 32; o <<= 1) {
        int u = __shfl_up_sync(~0u, s, o);
        if (lane >= o) s += u;
    }
    if (lane == 31) wsum[w] = s;
    __syncthreads();
    if (t < 32) {
        int ws = wsum[t];
        for (int o = 1; o < 32; o <<= 1) {
            int u = __shfl_up_sync(~0u, ws, o);
            if (t >= o) ws += u;
        }
        wsum[t] = ws;
    }
    __syncthreads();
    int excl = s - v + ((w > 0) ? wsum[w - 1] : 0) + g_boff[b];
    if (gid < N) {
        g_rowptr[gid] = excl;
        g_dinv[gid]   = rsqrtf((float)(v + 1));  // +1 self-loop
    }
}

__global__ void fill_kernel(const void* __restrict__ ei, int E, int N) {
    int e = blockIdx.x * blockDim.x + threadIdx.x;
    if (e < E) {
        int row = edge_at(ei, e);
        int col = edge_at(ei, (size_t)E + e);
        if ((unsigned)row < (unsigned)N && (unsigned)col < (unsigned)N) {
            int pos = g_rowptr[col] + atomicAdd(&g_fill[col], 1);
            g_csr_src[pos] = row;
        }
    }
}

// ---------------------------------------------------------------------------
// Tensor-core GEMM (tf32 wmma m16n16k8):
//   H[row] = half( (X[row] @ W) * dinv[row] )        (pre-scaled fp16 messages)
// Block = 128 threads = 4 warps; warp owns 16 rows x NOUT cols.
// ws[] holds the tf32 W chunk during the mainloop and is reused as the
// fp32 epilogue staging tile afterwards (same size: KC*NOUT = 64*NOUT).
// ---------------------------------------------------------------------------
template <int LAYER, int NOUT>
__global__ void __launch_bounds__(128) gemm_tc_kernel(const float* __restrict__ Xin,
                                                      const float* __restrict__ W,
                                                      int N) {
    constexpr int KD = 128, KC = 64;
    __shared__ __align__(16) float ws[KC * NOUT];

    const float* X = (LAYER == 1) ? Xin  : g_acc1;
    __half*      H = (LAYER == 1) ? g_h1 : g_h2;

    const int warp = threadIdx.x >> 5;
    const int lane = threadIdx.x & 31;
    const int row0 = blockIdx.x * 64 + warp * 16;
    const bool active = (row0 + 16 <= N);

    wmma::fragment<wmma::accumulator, 16, 16, 8, float> c[NOUT / 16];
#pragma unroll
    for (int i = 0; i < NOUT / 16; i++) wmma::fill_fragment(c[i], 0.0f);

    for (int kc = 0; kc < KD; kc += KC) {
        __syncthreads();
        for (int i = threadIdx.x; i < KC * NOUT; i += 128)
            ws[i] = wmma::__float_to_tf32(W[(size_t)(kc + i / NOUT) * NOUT + (i % NOUT)]);
        __syncthreads();
        if (active) {
#pragma unroll
            for (int k = 0; k < KC; k += 8) {
                wmma::fragment<wmma::matrix_a, 16, 16, 8, wmma::precision::tf32, wmma::row_major> a;
                wmma::load_matrix_sync(a, X + (size_t)row0 * KD + kc + k, KD);
#pragma unroll
                for (int i = 0; i < a.num_elements; i++)
                    a.x[i] = wmma::__float_to_tf32(a.x[i]);
#pragma unroll
                for (int nt = 0; nt < NOUT / 16; nt++) {
                    wmma::fragment<wmma::matrix_b, 16, 16, 8, wmma::precision::tf32, wmma::row_major> b;
                    wmma::load_matrix_sync(b, ws + k * NOUT + nt * 16, NOUT);
                    wmma::mma_sync(c[nt], a, b, c[nt]);
                }
            }
        }
    }

    __syncthreads();  // all warps done reading ws; safe to reuse as epilogue tile
    if (active) {
        float* tile = ws + warp * 16 * NOUT;
#pragma unroll
        for (int nt = 0; nt < NOUT / 16; nt++)
            wmma::store_matrix_sync(tile + nt * 16, c[nt], NOUT, wmma::mem_row_major);
        __syncwarp();

        constexpr int HV = NOUT / 32;  // halves per lane per row (4 or 2)
#pragma unroll 4
        for (int r = 0; r < 16; r++) {
            float d = g_dinv[row0 + r];
            const float* src = tile + r * NOUT + lane * HV;
            __half* dst = H + (size_t)(row0 + r) * NOUT + lane * HV;
            if (HV == 4) {
                float4 v = *reinterpret_cast<const float4*>(src);
                half2x2 p;
                p.a = __floats2half2_rn(v.x * d, v.y * d);
                p.b = __floats2half2_rn(v.z * d, v.w * d);
                *reinterpret_cast<half2x2*>(dst) = p;
            } else {
                float2 v = *reinterpret_cast<const float2*>(src);
                *reinterpret_cast<__half2*>(dst) = __floats2half2_rn(v.x * d, v.y * d);
            }
        }
    } else if (row0 < N) {
        // scalar tail (only if N % 16 != 0)
        for (int r = row0; r < N; r++) {
            float d = g_dinv[r];
            for (int col = lane; col < NOUT; col += 32) {
                float s = 0.0f;
                for (int k = 0; k < KD; k++)
                    s += X[(size_t)r * KD + k] * W[(size_t)k * NOUT + col];
                H[(size_t)r * NOUT + col] = __float2half(s * d);
            }
        }
    }
}

// ---------------------------------------------------------------------------
// Atomic-free aggregation, one warp per destination node, fp16 messages.
//   ACC[col] = (relu?)( dinv[col] * ( m[col] + sum m[src] ) + bias )
// where m[i] = h[i]*dinv[i] is already fp16-pre-scaled.
// ---------------------------------------------------------------------------
template <int F, bool RELU>
__global__ void __launch_bounds__(256) agg_kernel(const float* __restrict__ bias,
                                                  float* __restrict__ OUT2, int N) {
    const __half* HS  = (F == 128) ? g_h1   : g_h2;
    float*        ACC = (F == 128) ? g_acc1 : OUT2;
    constexpr int V = F / 32;  // halves per lane (4 or 2)

    int col  = (blockIdx.x * blockDim.x + threadIdx.x) >> 5;
    int lane = threadIdx.x & 31;
    if (col >= N) return;

    const int   start = g_rowptr[col];
    const int   cnt   = g_cnt[col];
    const float d     = g_dinv[col];

    float v[V];
    {   // self-loop message
        const __half* r = HS + (size_t)col * F + lane * V;
        if (V == 4) {
            half2x2 u = *reinterpret_cast<const half2x2*>(r);
            float2 f0 = __half22float2(u.a);
            float2 f1 = __half22float2(u.b);
            v[0] = f0.x; v[1] = f0.y; v[2] = f1.x; v[3] = f1.y;
        } else {
            float2 f = __half22float2(*reinterpret_cast<const __half2*>(r));
            v[0] = f.x; v[1] = f.y;
        }
    }

    int j = 0;
    for (; j + 4 <= cnt; j += 4) {
        int s0 = __ldg(&g_csr_src[start + j + 0]);
        int s1 = __ldg(&g_csr_src[start + j + 1]);
        int s2 = __ldg(&g_csr_src[start + j + 2]);
        int s3 = __ldg(&g_csr_src[start + j + 3]);
        if (V == 4) {
            half2x2 u0 = *reinterpret_cast<const half2x2*>(HS + (size_t)s0 * F + lane * 4);
            half2x2 u1 = *reinterpret_cast<const half2x2*>(HS + (size_t)s1 * F + lane * 4);
            half2x2 u2 = *reinterpret_cast<const half2x2*>(HS + (size_t)s2 * F + lane * 4);
            half2x2 u3 = *reinterpret_cast<const half2x2*>(HS + (size_t)s3 * F + lane * 4);
            float2 a0 = __half22float2(u0.a), b0 = __half22float2(u0.b);
            float2 a1 = __half22float2(u1.a), b1 = __half22float2(u1.b);
            float2 a2 = __half22float2(u2.a), b2 = __half22float2(u2.b);
            float2 a3 = __half22float2(u3.a), b3 = __half22float2(u3.b);
            v[0] += (a0.x + a1.x) + (a2.x + a3.x);
            v[1] += (a0.y + a1.y) + (a2.y + a3.y);
            v[2] += (b0.x + b1.x) + (b2.x + b3.x);
            v[3] += (b0.y + b1.y) + (b2.y + b3.y);
        } else {
            float2 f0 = __half22float2(*reinterpret_cast<const __half2*>(HS + (size_t)s0 * F + lane * 2));
            float2 f1 = __half22float2(*reinterpret_cast<const __half2*>(HS + (size_t)s1 * F + lane * 2));
            float2 f2 = __half22float2(*reinterpret_cast<const __half2*>(HS + (size_t)s2 * F + lane * 2));
            float2 f3 = __half22float2(*reinterpret_cast<const __half2*>(HS + (size_t)s3 * F + lane * 2));
            v[0] += (f0.x + f1.x) + (f2.x + f3.x);
            v[1] += (f0.y + f1.y) + (f2.y + f3.y);
        }
    }
    for (; j < cnt; j++) {
        int src = __ldg(&g_csr_src[start + j]);
        const __half* r = HS + (size_t)src * F + lane * V;
        if (V == 4) {
            half2x2 u = *reinterpret_cast<const half2x2*>(r);
            float2 f0 = __half22float2(u.a);
            float2 f1 = __half22float2(u.b);
            v[0] += f0.x; v[1] += f0.y; v[2] += f1.x; v[3] += f1.y;
        } else {
            float2 f = __half22float2(*reinterpret_cast<const __half2*>(r));
            v[0] += f.x; v[1] += f.y;
        }
    }

    float* o = ACC + (size_t)col * F + lane * V;
    if (V == 4) {
        float4 b = *reinterpret_cast<const float4*>(bias + lane * 4);
        float4 w;
        w.x = fmaf(v[0], d, b.x); w.y = fmaf(v[1], d, b.y);
        w.z = fmaf(v[2], d, b.z); w.w = fmaf(v[3], d, b.w);
        if (RELU) {
            w.x = fmaxf(w.x, 0.0f); w.y = fmaxf(w.y, 0.0f);
            w.z = fmaxf(w.z, 0.0f); w.w = fmaxf(w.w, 0.0f);
        }
        *reinterpret_cast<float4*>(o) = w;
    } else {
        float2 b = *reinterpret_cast<const float2*>(bias + lane * 2);
        float2 w;
        w.x = fmaf(v[0], d, b.x); w.y = fmaf(v[1], d, b.y);
        if (RELU) { w.x = fmaxf(w.x, 0.0f); w.y = fmaxf(w.y, 0.0f); }
        *reinterpret_cast<float2*>(o) = w;
    }
}

// ---------------------------------------------------------------------------
// Launch
// ---------------------------------------------------------------------------
extern "C" void kernel_launch(void* const* d_in, const int* in_sizes, int n_in,
                              void* d_out, int out_size) {
    const float* x   = (const float*)d_in[0];
    const void*  ei  = d_in[1];
    const float* W1  = (const float*)d_in[4];
    const float* b1  = (const float*)d_in[5];
    const float* W2  = (const float*)d_in[6];
    const float* b2  = (const float*)d_in[7];
    float*       out = (float*)d_out;

    const int N  = in_sizes[0] / 128;
    const int E  = in_sizes[1] / 2;
    const int NB = (N + 1023) / 1024;

    detect_kernel<<<1, 32>>>((const int*)ei);
    init_kernel<<<(N + 255) / 256, 256>>>(N);
    count_kernel<<<(E + 255) / 256, 256>>>(ei, E, N);
    scan_bsum_kernel<<<NB, 1024>>>(N);
    scan_boff_kernel<<<1, 64>>>(NB);
    scan_local_kernel<<<NB, 1024>>>(N);   // rowptr + dinv fused
    fill_kernel<<<(E + 255) / 256, 256>>>(ei, E, N);

    // Layer 1: h1 = half((x @ W1)*dinv) ; acc1 = relu(dinv*agg(h1) + b1)
    gemm_tc_kernel<1, 128><<<(N + 63) / 64, 128>>>(x, W1, N);
    agg_kernel<128, true><<<(N * 32 + 255) / 256, 256>>>(b1, nullptr, N);

    // Layer 2: h2 = half((acc1 @ W2)*dinv) ; out = dinv*agg(h2) + b2
    gemm_tc_kernel<2, 64><<<(N + 63) / 64, 128>>>(nullptr, W2, N);
    agg_kernel<64, false><<<(N * 32 + 255) / 256, 256>>>(b2, out, N);
}